// round 10
// baseline (speedup 1.0000x reference)
#include <cuda_runtime.h>
#include <math.h>

#define NLVL 3
#define NAA  3
#define NT   200
#define NCC  80
#define NOO  85
#define BSZ  8
#define MAXC 1000
#define CH   256
#define NCHUNK 4
#define CCH  64   // channels per chunk (conv)

#define CAND_BLOCKS 288   // 32 x 9
#define CONV_BLOCKS 268   // lvl0:200, lvl1:52, lvl2:16 (256 thr each)

// ---------------- scratch (device globals: no allocation allowed) ----------
// SELF-CLEANING INVARIANT: every kernel_launch leaves all scratch zeroed
// (tobj zeroed by bce after read; acc/cnt/bcnt reset by the fin block).
__device__ unsigned long long g_tobj[201600];     // packed (rowid<<32 | f32bits(max(iou,0)))
__device__ float g_part[NCHUNK * 201600];         // per-chunk partial obj logits (conv)
__device__ float g_acc[32];                       // per level stride 8: 0 lbox,1 C1,2 C2,3 S1,4 S2,5 fg
__device__ int   g_cnt[16];                       // per (level,anchor) candidate count
__device__ int   g_list[9 * MAXC];                // compacted candidate ids
__device__ int   g_bcnt;                          // bce completion counter

__constant__ int c_nx[3]    = {80, 40, 20};
__constant__ int c_P[3]     = {6400, 1600, 400};
__constant__ int c_toff[3]  = {0, 153600, 192000};
__constant__ int c_toff4[3] = {0, 38400, 48000};

// ---------------- helpers ---------------------------------------------------
__device__ __forceinline__ float d_sig(float x) { return 1.0f / (1.0f + expf(-x)); }

__device__ __forceinline__ float d_spp(float x) {
    float l = log1pf(expf(-fabsf(x)));
    return fmaxf(x, 0.0f) + l;
}

__device__ __forceinline__ void anchor_wh(int a, float* aw, float* ah) {
    const float H[3] = {0.70710678f, 1.0f, 1.41421356f};
    *aw = (32.0f / H[a]) / 8.0f;
    *ah = (32.0f * H[a]) / 8.0f;
}

__device__ __forceinline__ float d_ciou(float px, float py, float pw, float ph,
                                        float tx, float ty, float tw, float th) {
    const float EPS = 1e-9f;
    float b1x1 = px - pw * 0.5f, b1x2 = px + pw * 0.5f;
    float b1y1 = py - ph * 0.5f, b1y2 = py + ph * 0.5f;
    float b2x1 = tx - tw * 0.5f, b2x2 = tx + tw * 0.5f;
    float b2y1 = ty - th * 0.5f, b2y2 = ty + th * 0.5f;
    float iw = fmaxf(fminf(b1x2, b2x2) - fmaxf(b1x1, b2x1), 0.0f);
    float ih = fmaxf(fminf(b1y2, b2y2) - fmaxf(b1y1, b2y1), 0.0f);
    float inter = iw * ih;
    float uni = pw * ph + tw * th - inter + EPS;
    float iou = inter / uni;
    float cw = fmaxf(b1x2, b2x2) - fminf(b1x1, b2x1);
    float chh = fmaxf(b1y2, b2y2) - fminf(b1y1, b2y1);
    float c2 = cw * cw + chh * chh + EPS;
    float dx = b2x1 + b2x2 - b1x1 - b1x2;
    float dy = b2y1 + b2y2 - b1y1 - b1y2;
    float rho2 = (dx * dx + dy * dy) * 0.25f;
    float dat = atanf(tw / (th + EPS)) - atanf(pw / (ph + EPS));
    float v = 0.40528473456935108577f * dat * dat;  // 4/pi^2
    float alpha = v / (v - iou + (1.0f + EPS));
    return iou - (rho2 / c2 + v * alpha);
}

// ---------------- kernel 1: candidate mask + compaction ---------------------
__global__ void prep_kernel(const float* __restrict__ tg) {
    int idx = blockIdx.x * blockDim.x + threadIdx.x;
    if (idx >= NLVL * 5 * 600) return;
    int lvl = idx / 3000, rem = idx % 3000;
    int k = rem / 600, j = rem % 600;
    int a = j / NT, t = j % NT;
    float nx = (float)c_nx[lvl];
    float gx = tg[t * 6 + 2] * nx, gy = tg[t * 6 + 3] * nx;
    float gw = tg[t * 6 + 4] * nx, gh = tg[t * 6 + 5] * nx;
    float aw, ah; anchor_wh(a, &aw, &ah);
    float rw = gw / aw, rh = gh / ah;
    float mr = fmaxf(fmaxf(rw, 1.0f / rw), fmaxf(rh, 1.0f / rh));
    bool manc = mr < 2.91f;
    bool sel;
    float gxi = nx - gx, gyi = nx - gy;
    switch (k) {
        case 0: sel = true; break;
        case 1: sel = (fmodf(gx, 1.0f)  < 0.5f) && (gx  > 1.0f); break;
        case 2: sel = (fmodf(gy, 1.0f)  < 0.5f) && (gy  > 1.0f); break;
        case 3: sel = (fmodf(gxi, 1.0f) < 0.5f) && (gxi > 1.0f); break;
        default: sel = (fmodf(gyi, 1.0f) < 0.5f) && (gyi > 1.0f); break;
    }
    if (sel && manc) {
        int pos = atomicAdd(&g_cnt[lvl * 3 + a], 1);
        g_list[(lvl * 3 + a) * MAXC + pos] = k * 600 + j;
    }
}

// ---------------- kernel 2: FUSED conv + candidate GEMM ----------------------
// blocks [0, 288):  candidate gather-GEMM + iou + cls BCE  (round-5 path)
// blocks [288,556): full-grid objectness conv partials     (NCHUNK=4, 256 thr)
// Both roles co-resident in one wave -> conv's streaming warps fill cand's
// latency stalls; total DRAM bytes bound the node.
__global__ void __launch_bounds__(256) fused_kernel(
    const float* __restrict__ f0, const float* __restrict__ f1, const float* __restrict__ f2,
    const float* __restrict__ w0, const float* __restrict__ w1, const float* __restrict__ w2,
    const float* __restrict__ bp0, const float* __restrict__ bp1, const float* __restrict__ bp2,
    const float* __restrict__ tg)
{
    __shared__ __align__(16) float Ws[NOO][64];   // cand weights / conv wsm slice
    __shared__ float Xs[64][32];
    __shared__ float Ps[32][NOO + 3];
    __shared__ int   sm_b[32], sm_pos[32], sm_cls[32], sm_rid[32], sm_cell[32];
    __shared__ float sm_tb[32][4];
    __shared__ float s_lb, s_c1, s_c2;

    int tid = threadIdx.x;

    if (blockIdx.x >= CAND_BLOCKS) {
        // ================= conv role =================
        int bid = blockIdx.x - CAND_BLOCKS;
        int lvl, chunk, pb;
        if (bid < 200)      { lvl = 0; chunk = bid / 50; pb = bid % 50; }
        else if (bid < 252) { int r = bid - 200; lvl = 1; chunk = r / 13; pb = r % 13; }
        else                { int r = bid - 252; lvl = 2; chunk = r / 4;  pb = r % 4; }
        const float* feat = (lvl == 0) ? f0 : ((lvl == 1) ? f1 : f2);
        const float* wmat = (lvl == 0) ? w0 : ((lvl == 1) ? w1 : w2);
        float* wsm = &Ws[0][0];                    // [3][CCH] slice of Ws
        int c0 = chunk * CCH;
        if (tid < 3 * CCH) {
            int a = tid / CCH, c = tid % CCH;
            wsm[a * CCH + c] = wmat[(a * NOO + 4) * CH + c0 + c];
        }
        __syncthreads();

        int P4 = c_P[lvl] >> 2;
        int idx = pb * 256 + tid;
        if (idx >= BSZ * P4) return;
        int b = idx / P4, pf4 = idx - b * P4;

        const float4* fp = reinterpret_cast<const float4*>(feat)
                         + (size_t)(b * CH + c0) * (size_t)P4 + pf4;
        float4 a0 = make_float4(0.f, 0.f, 0.f, 0.f);
        float4 a1 = a0, a2 = a0;
#pragma unroll
        for (int cc = 0; cc < CCH; cc += 8) {
            float4 v[8];
#pragma unroll
            for (int u = 0; u < 8; u++) v[u] = fp[(size_t)(cc + u) * P4];
#pragma unroll
            for (int u = 0; u < 8; u++) {
                float wv0 = wsm[cc + u], wv1 = wsm[CCH + cc + u], wv2 = wsm[2 * CCH + cc + u];
                a0.x = fmaf(v[u].x, wv0, a0.x); a0.y = fmaf(v[u].y, wv0, a0.y);
                a0.z = fmaf(v[u].z, wv0, a0.z); a0.w = fmaf(v[u].w, wv0, a0.w);
                a1.x = fmaf(v[u].x, wv1, a1.x); a1.y = fmaf(v[u].y, wv1, a1.y);
                a1.z = fmaf(v[u].z, wv1, a1.z); a1.w = fmaf(v[u].w, wv1, a1.w);
                a2.x = fmaf(v[u].x, wv2, a2.x); a2.y = fmaf(v[u].y, wv2, a2.y);
                a2.z = fmaf(v[u].z, wv2, a2.z); a2.w = fmaf(v[u].w, wv2, a2.w);
            }
        }
        float4* gp = reinterpret_cast<float4*>(g_part) + (size_t)chunk * 50400;
        int base4 = c_toff4[lvl] + (b * 3) * P4 + pf4;
        gp[base4]          = a0;
        gp[base4 + P4]     = a1;
        gp[base4 + 2 * P4] = a2;
        return;
    }

    // ================= cand role (round-5 proven path) =================
    int la = blockIdx.x >> 5;
    int lvl = la / 3, a = la % 3;
    int n = g_cnt[la];
    int m0 = (blockIdx.x & 31) * 32;
    if (m0 >= n) return;
    int mcount = min(32, n - m0);
    const float* feat = (lvl == 0) ? f0 : ((lvl == 1) ? f1 : f2);
    const float* wmat = (lvl == 0) ? w0 : ((lvl == 1) ? w1 : w2);
    const float* bb   = (lvl == 0) ? bp0 : ((lvl == 1) ? bp1 : bp2);
    int nx = c_nx[lvl]; int P = c_P[lvl];
    if (tid == 0) { s_lb = 0.f; s_c1 = 0.f; s_c2 = 0.f; }
    if (tid < 32) {
        int m = tid;
        if (m < mcount) {
            int cid = g_list[la * MAXC + m0 + m];
            int k = cid / 600; int j = cid % 600; int t = j % NT;
            float img  = tg[t * 6 + 0], clsf = tg[t * 6 + 1];
            float gx = tg[t * 6 + 2] * (float)nx, gy = tg[t * 6 + 3] * (float)nx;
            float gw = tg[t * 6 + 4] * (float)nx, gh = tg[t * 6 + 5] * (float)nx;
            float offx = (k == 1) ? 0.5f : ((k == 3) ? -0.5f : 0.0f);
            float offy = (k == 2) ? 0.5f : ((k == 4) ? -0.5f : 0.0f);
            int gij_x = (int)(gx - offx);
            int gij_y = (int)(gy - offy);
            int gi = min(max(gij_x, 0), nx - 1);
            int gj = min(max(gij_y, 0), nx - 1);
            int b = (int)img;
            sm_b[m] = b; sm_pos[m] = gj * nx + gi;
            sm_cell[m] = ((b * NAA + a) * nx + gj) * nx + gi;
            sm_cls[m] = (int)clsf;
            sm_rid[m] = cid;
            sm_tb[m][0] = gx - (float)gij_x;
            sm_tb[m][1] = gy - (float)gij_y;
            sm_tb[m][2] = gw; sm_tb[m][3] = gh;
        } else { sm_b[m] = 0; sm_pos[m] = 0; }
    }
    __syncthreads();

    float acc[11];
#pragma unroll
    for (int r = 0; r < 11; r++) acc[r] = 0.0f;
    int wrp = tid >> 5, lane = tid & 31;

    for (int kc = 0; kc < 4; kc++) {
        for (int idx = tid; idx < NOO * 64; idx += 256) {
            int o = idx >> 6, c = idx & 63;
            Ws[o][c] = wmat[(a * NOO + o) * CH + kc * 64 + c];
        }
        {
            int m = tid & 31;
            int b = sm_b[m], pos = sm_pos[m];
            const float* fp = feat + ((size_t)b * CH + (size_t)kc * 64) * (size_t)P + pos;
#pragma unroll
            for (int r = 0; r < 8; r++) {
                int c = (tid >> 5) + r * 8;
                Xs[c][m] = fp[(size_t)c * P];
            }
        }
        __syncthreads();
#pragma unroll
        for (int c4 = 0; c4 < 16; c4++) {
            float x0 = Xs[c4 * 4 + 0][lane];
            float x1 = Xs[c4 * 4 + 1][lane];
            float x2 = Xs[c4 * 4 + 2][lane];
            float x3 = Xs[c4 * 4 + 3][lane];
#pragma unroll
            for (int r = 0; r < 11; r++) {
                int o = wrp + 8 * r;
                if (o < NOO) {
                    float4 wv = *reinterpret_cast<const float4*>(&Ws[o][c4 * 4]);
                    acc[r] = fmaf(x0, wv.x, fmaf(x1, wv.y, fmaf(x2, wv.z, fmaf(x3, wv.w, acc[r]))));
                }
            }
        }
        __syncthreads();
    }

#pragma unroll
    for (int r = 0; r < 11; r++) {
        int o = wrp + 8 * r;
        if (o < NOO) Ps[lane][o] = acc[r] + bb[a * NOO + o];
    }
    __syncthreads();

    int m = tid >> 3, s = tid & 7;
    unsigned gmask = 0xFFu << (8 * ((tid & 31) >> 3));
    if (m < mcount) {
        float spsum = 0.f, tspm = 0.f, tspp = 0.f;
        int cls = sm_cls[m];
        for (int c = s; c < NCC; c += 8) {
            float x = Ps[m][5 + c];
            float sp = d_spp(x);
            spsum += sp;
            if (c == cls) { tspp = sp; tspm = d_spp(-x); }
        }
        for (int off = 4; off; off >>= 1) {
            spsum += __shfl_down_sync(gmask, spsum, off, 8);
            tspm  += __shfl_down_sync(gmask, tspm,  off, 8);
            tspp  += __shfl_down_sync(gmask, tspp,  off, 8);
        }
        if (s == 0) {
            float aw, ah; anchor_wh(a, &aw, &ah);
            float px = d_sig(Ps[m][0]) * 2.0f - 0.5f;
            float py = d_sig(Ps[m][1]) * 2.0f - 0.5f;
            float sw = d_sig(Ps[m][2]) * 2.0f;
            float sh = d_sig(Ps[m][3]) * 2.0f;
            float pw = sw * sw * aw, ph = sh * sh * ah;
            float ci = d_ciou(px, py, pw, ph, sm_tb[m][0], sm_tb[m][1], sm_tb[m][2], sm_tb[m][3]);
            unsigned long long pk = ((unsigned long long)(unsigned)sm_rid[m] << 32)
                                  | (unsigned long long)__float_as_uint(fmaxf(ci, 0.0f));
            atomicMax(&g_tobj[c_toff[lvl] + sm_cell[m]], pk);
            atomicAdd(&s_lb, 1.0f - ci);
            atomicAdd(&s_c1, tspm);
            atomicAdd(&s_c2, spsum - tspp);
        }
    }
    __syncthreads();
    if (tid == 0) {
        atomicAdd(&g_acc[lvl * 8 + 0], s_lb);
        atomicAdd(&g_acc[lvl * 8 + 1], s_c1);
        atomicAdd(&g_acc[lvl * 8 + 2], s_c2);
    }
}

// ---------------- kernel 3: obj BCE + fused finalize + scratch cleanup -------
__global__ void __launch_bounds__(128) bce_kernel(
    const float* __restrict__ bp0, const float* __restrict__ bp1, const float* __restrict__ bp2,
    float* __restrict__ out)
{
    __shared__ float rbuf[3][4];
    int blk = blockIdx.x;
    int tid = threadIdx.x;
    int lvl = (blk < 300) ? 0 : ((blk < 375) ? 1 : 2);
    int gidx = blk * 128 + tid;
    float s1 = 0.f, s2 = 0.f, fg = 0.f;
    if (gidx < 50400) {
        int P4 = c_P[lvl] >> 2;
        int rel = gidx - c_toff4[lvl];
        int a = (rel / P4) % 3;
        const float* bb = (lvl == 0) ? bp0 : ((lvl == 1) ? bp1 : bp2);
        float bias = bb[a * NOO + 4];
        const float4* gp = reinterpret_cast<const float4*>(g_part);
        float4 p0 = gp[gidx];
        float4 p1 = gp[50400 + gidx];
        float4 p2 = gp[2 * 50400 + gidx];
        float4 p3 = gp[3 * 50400 + gidx];
        float xs[4] = {p0.x + p1.x + p2.x + p3.x + bias,
                       p0.y + p1.y + p2.y + p3.y + bias,
                       p0.z + p1.z + p2.z + p3.z + bias,
                       p0.w + p1.w + p2.w + p3.w + bias};
        unsigned long long* tp = &g_tobj[(size_t)gidx * 4];
#pragma unroll
        for (int j = 0; j < 4; j++) {
            float x = xs[j];
            float t = __uint_as_float((unsigned)tp[j]);
            tp[j] = 0ull;   // self-clean for the next call
            float l = log1pf(expf(-fabsf(x)));
            float spp = fmaxf(x, 0.f) + l;
            float spm = fmaxf(-x, 0.f) + l;
            s1 += t * spm;
            s2 += (1.0f - t) * spp;
            fg += (t > 0.f) ? 1.0f : 0.0f;
        }
    }
    for (int off = 16; off; off >>= 1) {
        s1 += __shfl_down_sync(0xffffffffu, s1, off);
        s2 += __shfl_down_sync(0xffffffffu, s2, off);
        fg += __shfl_down_sync(0xffffffffu, fg, off);
    }
    if ((tid & 31) == 0) { rbuf[0][tid >> 5] = s1; rbuf[1][tid >> 5] = s2; rbuf[2][tid >> 5] = fg; }
    __syncthreads();
    bool last = false;
    if (tid == 0) {
        float t1 = 0.f, t2 = 0.f, t3 = 0.f;
        for (int i = 0; i < 4; i++) { t1 += rbuf[0][i]; t2 += rbuf[1][i]; t3 += rbuf[2][i]; }
        atomicAdd(&g_acc[lvl * 8 + 3], t1);
        atomicAdd(&g_acc[lvl * 8 + 4], t2);
        atomicAdd(&g_acc[lvl * 8 + 5], t3);
        __threadfence();
        int done = atomicAdd(&g_bcnt, 1);
        last = (done == 393);
    }
    if (last) {
        float lbox = 0.f, lobj = 0.f, lcls = 0.f;
        const float bal[3] = {4.0f, 1.0f, 0.25f};
        for (int l = 0; l < 3; l++) {
            float nv = (float)(g_cnt[l * 3] + g_cnt[l * 3 + 1] + g_cnt[l * 3 + 2]);
            float lb = atomicAdd(&g_acc[l * 8 + 0], 0.0f);
            float c1 = atomicAdd(&g_acc[l * 8 + 1], 0.0f);
            float c2 = atomicAdd(&g_acc[l * 8 + 2], 0.0f);
            float S1 = atomicAdd(&g_acc[l * 8 + 3], 0.0f);
            float S2 = atomicAdd(&g_acc[l * 8 + 4], 0.0f);
            float fgc = atomicAdd(&g_acc[l * 8 + 5], 0.0f);
            lbox += lb / fmaxf(nv, 1.0f);
            float pwc = nv * (float)(NCC - 1) * 0.5f / fmaxf(nv, 2.0f);
            lcls += (pwc * c1 + c2) / fmaxf(nv * (float)NCC, 1.0f);
            float cnt = (float)(BSZ * NAA * c_P[l]);
            float bg = cnt - fgc;
            float pwo = bg * 0.5f / fmaxf(fgc, 2.0f);
            lobj += (pwo * S1 + S2) / cnt * bal[l];
        }
        out[0] = lbox * 0.05f;
        out[1] = lobj * 1.0f;
        out[2] = lcls * 0.5f;
        for (int i = 0; i < 32; i++) g_acc[i] = 0.0f;
        for (int i = 0; i < 16; i++) g_cnt[i] = 0;
        g_bcnt = 0;
    }
}

// ---------------- launch -----------------------------------------------------
extern "C" void kernel_launch(void* const* d_in, const int* in_sizes, int n_in,
                              void* d_out, int out_size) {
    const float *f[3], *w[3], *b[3], *tg;
    if (n_in >= 10 && in_sizes[1] == 65280) {
        f[0] = (const float*)d_in[0]; w[0] = (const float*)d_in[1]; b[0] = (const float*)d_in[2];
        f[1] = (const float*)d_in[3]; w[1] = (const float*)d_in[4]; b[1] = (const float*)d_in[5];
        f[2] = (const float*)d_in[6]; w[2] = (const float*)d_in[7]; b[2] = (const float*)d_in[8];
        tg = (const float*)d_in[9];
    } else {
        f[0] = (const float*)d_in[0]; f[1] = (const float*)d_in[1]; f[2] = (const float*)d_in[2];
        w[0] = (const float*)d_in[3]; w[1] = (const float*)d_in[4]; w[2] = (const float*)d_in[5];
        b[0] = (const float*)d_in[6]; b[1] = (const float*)d_in[7]; b[2] = (const float*)d_in[8];
        tg = (const float*)d_in[9];
    }

    prep_kernel<<<36, 256>>>(tg);
    fused_kernel<<<CAND_BLOCKS + CONV_BLOCKS, 256>>>(f[0], f[1], f[2],
                                                     w[0], w[1], w[2],
                                                     b[0], b[1], b[2], tg);
    bce_kernel<<<394, 128>>>(b[0], b[1], b[2], (float*)d_out);
}

// round 11
// speedup vs baseline: 1.1412x; 1.1412x over previous
#include <cuda_runtime.h>
#include <math.h>

#define NLVL 3
#define NAA  3
#define NT   200
#define NCC  80
#define NOO  85
#define BSZ  8
#define MAXC 1000
#define CH   256
#define NCHUNK 4
#define CCH  64   // channels per chunk (conv)

// dynamic smem layout for cand_kernel:
//   Ws: 2 buffers x 85*64 floats  (43.5 KB)
//   Xs: 2 buffers x 64*32 floats  (16 KB)  -- Ps[32][88] aliases Xs after FMA
#define WS_STRIDE (NOO * 64)
#define XS_STRIDE (64 * 32)
#define CAND_SMEM ((2 * WS_STRIDE + 2 * XS_STRIDE) * 4)

// ---------------- scratch (device globals: no allocation allowed) ----------
// SELF-CLEANING INVARIANT: every kernel_launch leaves all scratch zeroed.
__device__ unsigned long long g_tobj[201600];
__device__ float g_part[NCHUNK * 201600];
__device__ float g_acc[32];
__device__ int   g_cnt[16];
__device__ int   g_list[9 * MAXC];
__device__ int   g_bcnt;

__constant__ int c_nx[3]    = {80, 40, 20};
__constant__ int c_P[3]     = {6400, 1600, 400};
__constant__ int c_toff[3]  = {0, 153600, 192000};
__constant__ int c_toff4[3] = {0, 38400, 48000};

// ---------------- helpers ---------------------------------------------------
__device__ __forceinline__ float d_sig(float x) { return 1.0f / (1.0f + expf(-x)); }

__device__ __forceinline__ float d_spp(float x) {
    float l = log1pf(expf(-fabsf(x)));
    return fmaxf(x, 0.0f) + l;
}

__device__ __forceinline__ void anchor_wh(int a, float* aw, float* ah) {
    const float H[3] = {0.70710678f, 1.0f, 1.41421356f};
    *aw = (32.0f / H[a]) / 8.0f;
    *ah = (32.0f * H[a]) / 8.0f;
}

__device__ __forceinline__ float d_ciou(float px, float py, float pw, float ph,
                                        float tx, float ty, float tw, float th) {
    const float EPS = 1e-9f;
    float b1x1 = px - pw * 0.5f, b1x2 = px + pw * 0.5f;
    float b1y1 = py - ph * 0.5f, b1y2 = py + ph * 0.5f;
    float b2x1 = tx - tw * 0.5f, b2x2 = tx + tw * 0.5f;
    float b2y1 = ty - th * 0.5f, b2y2 = ty + th * 0.5f;
    float iw = fmaxf(fminf(b1x2, b2x2) - fmaxf(b1x1, b2x1), 0.0f);
    float ih = fmaxf(fminf(b1y2, b2y2) - fmaxf(b1y1, b2y1), 0.0f);
    float inter = iw * ih;
    float uni = pw * ph + tw * th - inter + EPS;
    float iou = inter / uni;
    float cw = fmaxf(b1x2, b2x2) - fminf(b1x1, b2x1);
    float chh = fmaxf(b1y2, b2y2) - fminf(b1y1, b2y1);
    float c2 = cw * cw + chh * chh + EPS;
    float dx = b2x1 + b2x2 - b1x1 - b1x2;
    float dy = b2y1 + b2y2 - b1y1 - b1y2;
    float rho2 = (dx * dx + dy * dy) * 0.25f;
    float dat = atanf(tw / (th + EPS)) - atanf(pw / (ph + EPS));
    float v = 0.40528473456935108577f * dat * dat;  // 4/pi^2
    float alpha = v / (v - iou + (1.0f + EPS));
    return iou - (rho2 / c2 + v * alpha);
}

// ---------------- kernel 1: candidate mask + compaction ---------------------
__global__ void prep_kernel(const float* __restrict__ tg) {
    int idx = blockIdx.x * blockDim.x + threadIdx.x;
    if (idx >= NLVL * 5 * 600) return;
    int lvl = idx / 3000, rem = idx % 3000;
    int k = rem / 600, j = rem % 600;
    int a = j / NT, t = j % NT;
    float nx = (float)c_nx[lvl];
    float gx = tg[t * 6 + 2] * nx, gy = tg[t * 6 + 3] * nx;
    float gw = tg[t * 6 + 4] * nx, gh = tg[t * 6 + 5] * nx;
    float aw, ah; anchor_wh(a, &aw, &ah);
    float rw = gw / aw, rh = gh / ah;
    float mr = fmaxf(fmaxf(rw, 1.0f / rw), fmaxf(rh, 1.0f / rh));
    bool manc = mr < 2.91f;
    bool sel;
    float gxi = nx - gx, gyi = nx - gy;
    switch (k) {
        case 0: sel = true; break;
        case 1: sel = (fmodf(gx, 1.0f)  < 0.5f) && (gx  > 1.0f); break;
        case 2: sel = (fmodf(gy, 1.0f)  < 0.5f) && (gy  > 1.0f); break;
        case 3: sel = (fmodf(gxi, 1.0f) < 0.5f) && (gxi > 1.0f); break;
        default: sel = (fmodf(gyi, 1.0f) < 0.5f) && (gyi > 1.0f); break;
    }
    if (sel && manc) {
        int pos = atomicAdd(&g_cnt[lvl * 3 + a], 1);
        g_list[(lvl * 3 + a) * MAXC + pos] = k * 600 + j;
    }
}

// ---------------- kernel 2: software-pipelined candidate GEMM ---------------
// grid (32, 9), 256 threads, 32 candidates/block. Double-buffered Ws + Xs:
// next stage's weight/gather loads issue before the current FMA loop.
__global__ void __launch_bounds__(256) cand_kernel(
    const float* __restrict__ f0, const float* __restrict__ f1, const float* __restrict__ f2,
    const float* __restrict__ w0, const float* __restrict__ w1, const float* __restrict__ w2,
    const float* __restrict__ bp0, const float* __restrict__ bp1, const float* __restrict__ bp2,
    const float* __restrict__ tg)
{
    extern __shared__ float smb[];
    float* WsA = smb;                        // [2][85*64]
    float* XsA = smb + 2 * WS_STRIDE;        // [2][64*32]
    float* Ps  = XsA;                        // [32][88], aliases Xs after FMA

    __shared__ int   sm_b[32], sm_pos[32], sm_cls[32], sm_rid[32], sm_cell[32];
    __shared__ float sm_tb[32][4];
    __shared__ float s_lb, s_c1, s_c2;

    int la = blockIdx.y;
    int lvl = la / 3, a = la % 3;
    int n = g_cnt[la];
    int m0 = blockIdx.x * 32;
    if (m0 >= n) return;
    int mcount = min(32, n - m0);
    const float* feat = (lvl == 0) ? f0 : ((lvl == 1) ? f1 : f2);
    const float* wmat = (lvl == 0) ? w0 : ((lvl == 1) ? w1 : w2);
    const float* bb   = (lvl == 0) ? bp0 : ((lvl == 1) ? bp1 : bp2);
    int nx = c_nx[lvl]; int P = c_P[lvl];
    int tid = threadIdx.x;
    if (tid == 0) { s_lb = 0.f; s_c1 = 0.f; s_c2 = 0.f; }
    if (tid < 32) {
        int m = tid;
        if (m < mcount) {
            int cid = g_list[la * MAXC + m0 + m];
            int k = cid / 600; int j = cid % 600; int t = j % NT;
            float img  = tg[t * 6 + 0], clsf = tg[t * 6 + 1];
            float gx = tg[t * 6 + 2] * (float)nx, gy = tg[t * 6 + 3] * (float)nx;
            float gw = tg[t * 6 + 4] * (float)nx, gh = tg[t * 6 + 5] * (float)nx;
            float offx = (k == 1) ? 0.5f : ((k == 3) ? -0.5f : 0.0f);
            float offy = (k == 2) ? 0.5f : ((k == 4) ? -0.5f : 0.0f);
            int gij_x = (int)(gx - offx);
            int gij_y = (int)(gy - offy);
            int gi = min(max(gij_x, 0), nx - 1);
            int gj = min(max(gij_y, 0), nx - 1);
            int b = (int)img;
            sm_b[m] = b; sm_pos[m] = gj * nx + gi;
            sm_cell[m] = ((b * NAA + a) * nx + gj) * nx + gi;
            sm_cls[m] = (int)clsf;
            sm_rid[m] = cid;
            sm_tb[m][0] = gx - (float)gij_x;
            sm_tb[m][1] = gy - (float)gij_y;
            sm_tb[m][2] = gw; sm_tb[m][3] = gh;
        } else { sm_b[m] = 0; sm_pos[m] = 0; }
    }
    __syncthreads();

    int wrp = tid >> 5, lane = tid & 31;
    int gm = tid & 31, gcb = tid >> 5;     // gather role: candidate gm, channel base gcb
    const float* fp = feat + (size_t)sm_b[gm] * CH * (size_t)P + sm_pos[gm];
    // weight source as float4: row (a*85+o) has 64 float4s; stage kc offset kc*16
    const float4* wsrc = reinterpret_cast<const float4*>(wmat) + (size_t)a * NOO * 64;

    // ---- stage 0 direct fill ----
    {
        float4* wd = reinterpret_cast<float4*>(WsA);
        for (int i = tid; i < NOO * 16; i += 256)
            wd[i] = wsrc[(i >> 4) * 64 + (i & 15)];
#pragma unroll
        for (int r = 0; r < 8; r++)
            XsA[(gcb + 8 * r) * 32 + gm] = fp[(size_t)(gcb + 8 * r) * P];
    }
    __syncthreads();

    float acc[11];
#pragma unroll
    for (int r = 0; r < 11; r++) acc[r] = 0.0f;

    for (int kc = 0; kc < 4; kc++) {
        float* Wcur = WsA + (kc & 1) * WS_STRIDE;
        float* Xcur = XsA + (kc & 1) * XS_STRIDE;

        // prefetch next stage into registers (latency covered by FMA below)
        float xreg[8];
        float4 wreg[6];
        int widx[6];
        if (kc < 3) {
            int kn = kc + 1;
#pragma unroll
            for (int r = 0; r < 8; r++)
                xreg[r] = fp[(size_t)(kn * 64 + gcb + 8 * r) * P];
#pragma unroll
            for (int j = 0; j < 6; j++) {
                int i = tid + j * 256;
                widx[j] = i;
                if (i < NOO * 16)
                    wreg[j] = wsrc[(i >> 4) * 64 + kn * 16 + (i & 15)];
            }
        }

        // FMA over current buffers
#pragma unroll
        for (int c4 = 0; c4 < 16; c4++) {
            float x0 = Xcur[(c4 * 4 + 0) * 32 + lane];
            float x1 = Xcur[(c4 * 4 + 1) * 32 + lane];
            float x2 = Xcur[(c4 * 4 + 2) * 32 + lane];
            float x3 = Xcur[(c4 * 4 + 3) * 32 + lane];
#pragma unroll
            for (int r = 0; r < 11; r++) {
                int o = wrp + 8 * r;
                if (o < NOO) {
                    float4 wv = *reinterpret_cast<const float4*>(&Wcur[o * 64 + c4 * 4]);
                    acc[r] = fmaf(x0, wv.x, fmaf(x1, wv.y, fmaf(x2, wv.z, fmaf(x3, wv.w, acc[r]))));
                }
            }
        }

        // drain prefetch into the alternate buffers
        if (kc < 3) {
            float* Wnxt = WsA + ((kc + 1) & 1) * WS_STRIDE;
            float* Xnxt = XsA + ((kc + 1) & 1) * XS_STRIDE;
#pragma unroll
            for (int r = 0; r < 8; r++)
                Xnxt[(gcb + 8 * r) * 32 + gm] = xreg[r];
            float4* wd = reinterpret_cast<float4*>(Wnxt);
#pragma unroll
            for (int j = 0; j < 6; j++)
                if (widx[j] < NOO * 16) wd[widx[j]] = wreg[j];
        }
        __syncthreads();
    }

    // write logits (+bias) into Ps (aliases Xs; all stages done, synced)
#pragma unroll
    for (int r = 0; r < 11; r++) {
        int o = wrp + 8 * r;
        if (o < NOO) Ps[lane * 88 + o] = acc[r] + bb[a * NOO + o];
    }
    __syncthreads();

    // epilogue: 8 threads per candidate
    int m = tid >> 3, s = tid & 7;
    unsigned gmask = 0xFFu << (8 * ((tid & 31) >> 3));
    if (m < mcount) {
        float spsum = 0.f, tspm = 0.f, tspp = 0.f;
        int cls = sm_cls[m];
        for (int c = s; c < NCC; c += 8) {
            float x = Ps[m * 88 + 5 + c];
            float sp = d_spp(x);
            spsum += sp;
            if (c == cls) { tspp = sp; tspm = d_spp(-x); }
        }
        for (int off = 4; off; off >>= 1) {
            spsum += __shfl_down_sync(gmask, spsum, off, 8);
            tspm  += __shfl_down_sync(gmask, tspm,  off, 8);
            tspp  += __shfl_down_sync(gmask, tspp,  off, 8);
        }
        if (s == 0) {
            float aw, ah; anchor_wh(a, &aw, &ah);
            float px = d_sig(Ps[m * 88 + 0]) * 2.0f - 0.5f;
            float py = d_sig(Ps[m * 88 + 1]) * 2.0f - 0.5f;
            float sw = d_sig(Ps[m * 88 + 2]) * 2.0f;
            float sh = d_sig(Ps[m * 88 + 3]) * 2.0f;
            float pw = sw * sw * aw, ph = sh * sh * ah;
            float ci = d_ciou(px, py, pw, ph, sm_tb[m][0], sm_tb[m][1], sm_tb[m][2], sm_tb[m][3]);
            unsigned long long pk = ((unsigned long long)(unsigned)sm_rid[m] << 32)
                                  | (unsigned long long)__float_as_uint(fmaxf(ci, 0.0f));
            atomicMax(&g_tobj[c_toff[lvl] + sm_cell[m]], pk);
            atomicAdd(&s_lb, 1.0f - ci);
            atomicAdd(&s_c1, tspm);
            atomicAdd(&s_c2, spsum - tspp);
        }
    }
    __syncthreads();
    if (tid == 0) {
        atomicAdd(&g_acc[lvl * 8 + 0], s_lb);
        atomicAdd(&g_acc[lvl * 8 + 1], s_c1);
        atomicAdd(&g_acc[lvl * 8 + 2], s_c2);
    }
}

// ---------------- kernel 3: fused full-grid objectness conv (partials) ------
__global__ void __launch_bounds__(128) conv_kernel(
    const float* __restrict__ f0, const float* __restrict__ f1, const float* __restrict__ f2,
    const float* __restrict__ w0, const float* __restrict__ w1, const float* __restrict__ w2)
{
    __shared__ float wsm[3][CCH];
    int bid = blockIdx.x;
    int tid = threadIdx.x;
    int lvl, chunk, pb;
    if (bid < 400)      { lvl = 0; chunk = bid / 100; pb = bid % 100; }
    else if (bid < 500) { int r = bid - 400; lvl = 1; chunk = r / 25; pb = r % 25; }
    else                { int r = bid - 500; lvl = 2; chunk = r / 7;  pb = r % 7; }
    const float* feat = (lvl == 0) ? f0 : ((lvl == 1) ? f1 : f2);
    const float* wmat = (lvl == 0) ? w0 : ((lvl == 1) ? w1 : w2);
    int c0 = chunk * CCH;
    for (int i = tid; i < 3 * CCH; i += 128) {
        int a = i / CCH, c = i % CCH;
        wsm[a][c] = wmat[(a * NOO + 4) * CH + c0 + c];
    }
    __syncthreads();

    int P4 = c_P[lvl] >> 2;
    int idx = pb * 128 + tid;
    if (idx >= BSZ * P4) return;
    int b = idx / P4, pf4 = idx - b * P4;

    const float4* fp = reinterpret_cast<const float4*>(feat)
                     + (size_t)(b * CH + c0) * (size_t)P4 + pf4;
    float4 a0 = make_float4(0.f, 0.f, 0.f, 0.f);
    float4 a1 = a0, a2 = a0;
#pragma unroll
    for (int cc = 0; cc < CCH; cc += 8) {
        float4 v[8];
#pragma unroll
        for (int u = 0; u < 8; u++) v[u] = fp[(size_t)(cc + u) * P4];
#pragma unroll
        for (int u = 0; u < 8; u++) {
            float wv0 = wsm[0][cc + u], wv1 = wsm[1][cc + u], wv2 = wsm[2][cc + u];
            a0.x = fmaf(v[u].x, wv0, a0.x); a0.y = fmaf(v[u].y, wv0, a0.y);
            a0.z = fmaf(v[u].z, wv0, a0.z); a0.w = fmaf(v[u].w, wv0, a0.w);
            a1.x = fmaf(v[u].x, wv1, a1.x); a1.y = fmaf(v[u].y, wv1, a1.y);
            a1.z = fmaf(v[u].z, wv1, a1.z); a1.w = fmaf(v[u].w, wv1, a1.w);
            a2.x = fmaf(v[u].x, wv2, a2.x); a2.y = fmaf(v[u].y, wv2, a2.y);
            a2.z = fmaf(v[u].z, wv2, a2.z); a2.w = fmaf(v[u].w, wv2, a2.w);
        }
    }
    float4* gp = reinterpret_cast<float4*>(g_part) + (size_t)chunk * 50400;
    int base4 = c_toff4[lvl] + (b * 3) * P4 + pf4;
    gp[base4]          = a0;
    gp[base4 + P4]     = a1;
    gp[base4 + 2 * P4] = a2;
}

// ---------------- kernel 4: obj BCE + fused finalize + scratch cleanup -------
__global__ void __launch_bounds__(128) bce_kernel(
    const float* __restrict__ bp0, const float* __restrict__ bp1, const float* __restrict__ bp2,
    float* __restrict__ out)
{
    __shared__ float rbuf[3][4];
    int blk = blockIdx.x;
    int tid = threadIdx.x;
    int lvl = (blk < 300) ? 0 : ((blk < 375) ? 1 : 2);
    int gidx = blk * 128 + tid;
    float s1 = 0.f, s2 = 0.f, fg = 0.f;
    if (gidx < 50400) {
        int P4 = c_P[lvl] >> 2;
        int rel = gidx - c_toff4[lvl];
        int a = (rel / P4) % 3;
        const float* bb = (lvl == 0) ? bp0 : ((lvl == 1) ? bp1 : bp2);
        float bias = bb[a * NOO + 4];
        const float4* gp = reinterpret_cast<const float4*>(g_part);
        float4 p0 = gp[gidx];
        float4 p1 = gp[50400 + gidx];
        float4 p2 = gp[2 * 50400 + gidx];
        float4 p3 = gp[3 * 50400 + gidx];
        float xs[4] = {p0.x + p1.x + p2.x + p3.x + bias,
                       p0.y + p1.y + p2.y + p3.y + bias,
                       p0.z + p1.z + p2.z + p3.z + bias,
                       p0.w + p1.w + p2.w + p3.w + bias};
        unsigned long long* tp = &g_tobj[(size_t)gidx * 4];
#pragma unroll
        for (int j = 0; j < 4; j++) {
            float x = xs[j];
            float t = __uint_as_float((unsigned)tp[j]);
            tp[j] = 0ull;   // self-clean for the next call
            float l = log1pf(expf(-fabsf(x)));
            float spp = fmaxf(x, 0.f) + l;
            float spm = fmaxf(-x, 0.f) + l;
            s1 += t * spm;
            s2 += (1.0f - t) * spp;
            fg += (t > 0.f) ? 1.0f : 0.0f;
        }
    }
    for (int off = 16; off; off >>= 1) {
        s1 += __shfl_down_sync(0xffffffffu, s1, off);
        s2 += __shfl_down_sync(0xffffffffu, s2, off);
        fg += __shfl_down_sync(0xffffffffu, fg, off);
    }
    if ((tid & 31) == 0) { rbuf[0][tid >> 5] = s1; rbuf[1][tid >> 5] = s2; rbuf[2][tid >> 5] = fg; }
    __syncthreads();
    bool last = false;
    if (tid == 0) {
        float t1 = 0.f, t2 = 0.f, t3 = 0.f;
        for (int i = 0; i < 4; i++) { t1 += rbuf[0][i]; t2 += rbuf[1][i]; t3 += rbuf[2][i]; }
        atomicAdd(&g_acc[lvl * 8 + 3], t1);
        atomicAdd(&g_acc[lvl * 8 + 4], t2);
        atomicAdd(&g_acc[lvl * 8 + 5], t3);
        __threadfence();
        int done = atomicAdd(&g_bcnt, 1);
        last = (done == 393);
    }
    if (last) {
        float lbox = 0.f, lobj = 0.f, lcls = 0.f;
        const float bal[3] = {4.0f, 1.0f, 0.25f};
        for (int l = 0; l < 3; l++) {
            float nv = (float)(g_cnt[l * 3] + g_cnt[l * 3 + 1] + g_cnt[l * 3 + 2]);
            float lb = atomicAdd(&g_acc[l * 8 + 0], 0.0f);
            float c1 = atomicAdd(&g_acc[l * 8 + 1], 0.0f);
            float c2 = atomicAdd(&g_acc[l * 8 + 2], 0.0f);
            float S1 = atomicAdd(&g_acc[l * 8 + 3], 0.0f);
            float S2 = atomicAdd(&g_acc[l * 8 + 4], 0.0f);
            float fgc = atomicAdd(&g_acc[l * 8 + 5], 0.0f);
            lbox += lb / fmaxf(nv, 1.0f);
            float pwc = nv * (float)(NCC - 1) * 0.5f / fmaxf(nv, 2.0f);
            lcls += (pwc * c1 + c2) / fmaxf(nv * (float)NCC, 1.0f);
            float cnt = (float)(BSZ * NAA * c_P[l]);
            float bg = cnt - fgc;
            float pwo = bg * 0.5f / fmaxf(fgc, 2.0f);
            lobj += (pwo * S1 + S2) / cnt * bal[l];
        }
        out[0] = lbox * 0.05f;
        out[1] = lobj * 1.0f;
        out[2] = lcls * 0.5f;
        for (int i = 0; i < 32; i++) g_acc[i] = 0.0f;
        for (int i = 0; i < 16; i++) g_cnt[i] = 0;
        g_bcnt = 0;
    }
}

// ---------------- launch -----------------------------------------------------
extern "C" void kernel_launch(void* const* d_in, const int* in_sizes, int n_in,
                              void* d_out, int out_size) {
    const float *f[3], *w[3], *b[3], *tg;
    if (n_in >= 10 && in_sizes[1] == 65280) {
        f[0] = (const float*)d_in[0]; w[0] = (const float*)d_in[1]; b[0] = (const float*)d_in[2];
        f[1] = (const float*)d_in[3]; w[1] = (const float*)d_in[4]; b[1] = (const float*)d_in[5];
        f[2] = (const float*)d_in[6]; w[2] = (const float*)d_in[7]; b[2] = (const float*)d_in[8];
        tg = (const float*)d_in[9];
    } else {
        f[0] = (const float*)d_in[0]; f[1] = (const float*)d_in[1]; f[2] = (const float*)d_in[2];
        w[0] = (const float*)d_in[3]; w[1] = (const float*)d_in[4]; w[2] = (const float*)d_in[5];
        b[0] = (const float*)d_in[6]; b[1] = (const float*)d_in[7]; b[2] = (const float*)d_in[8];
        tg = (const float*)d_in[9];
    }

    static bool s_init = false;
    if (!s_init) {
        cudaFuncSetAttribute(cand_kernel,
                             cudaFuncAttributeMaxDynamicSharedMemorySize, CAND_SMEM);
        s_init = true;
    }

    prep_kernel<<<36, 256>>>(tg);
    conv_kernel<<<528, 128>>>(f[0], f[1], f[2], w[0], w[1], w[2]);
    cand_kernel<<<dim3(32, 9), 256, CAND_SMEM>>>(f[0], f[1], f[2], w[0], w[1], w[2],
                                                 b[0], b[1], b[2], tg);
    bce_kernel<<<394, 128>>>(b[0], b[1], b[2], (float*)d_out);
}

// round 12
// speedup vs baseline: 1.2099x; 1.0602x over previous
#include <cuda_runtime.h>
#include <math.h>

#define NLVL 3
#define NAA  3
#define NT   200
#define NCC  80
#define NOO  85
#define BSZ  8
#define MAXC 1000
#define CH   256
#define NCHUNK 8
#define CCH  32   // channels per chunk (conv)

#define CONV_BLOCKS 1056  // lvl0: 8*100, lvl1: 8*25, lvl2: 8*7
#define PREP_BLOCKS 71    // 71*128 >= 9000

// dynamic smem layout for cand_kernel (round-11 pipelined version):
#define WS_STRIDE (NOO * 64)
#define XS_STRIDE (64 * 32)
#define CAND_SMEM ((2 * WS_STRIDE + 2 * XS_STRIDE) * 4)

// ---------------- scratch (device globals: no allocation allowed) ----------
// SELF-CLEANING INVARIANT: every kernel_launch leaves all scratch zeroed.
__device__ unsigned long long g_tobj[201600];
__device__ float g_part[NCHUNK * 201600];
__device__ float g_acc[32];
__device__ int   g_cnt[16];
__device__ int   g_list[9 * MAXC];
__device__ int   g_bcnt;

__constant__ int c_nx[3]    = {80, 40, 20};
__constant__ int c_P[3]     = {6400, 1600, 400};
__constant__ int c_toff[3]  = {0, 153600, 192000};
__constant__ int c_toff4[3] = {0, 38400, 48000};

// ---------------- helpers ---------------------------------------------------
__device__ __forceinline__ float d_sig(float x) { return 1.0f / (1.0f + expf(-x)); }

__device__ __forceinline__ float d_spp(float x) {
    float l = log1pf(expf(-fabsf(x)));
    return fmaxf(x, 0.0f) + l;
}

__device__ __forceinline__ void anchor_wh(int a, float* aw, float* ah) {
    const float H[3] = {0.70710678f, 1.0f, 1.41421356f};
    *aw = (32.0f / H[a]) / 8.0f;
    *ah = (32.0f * H[a]) / 8.0f;
}

__device__ __forceinline__ float d_ciou(float px, float py, float pw, float ph,
                                        float tx, float ty, float tw, float th) {
    const float EPS = 1e-9f;
    float b1x1 = px - pw * 0.5f, b1x2 = px + pw * 0.5f;
    float b1y1 = py - ph * 0.5f, b1y2 = py + ph * 0.5f;
    float b2x1 = tx - tw * 0.5f, b2x2 = tx + tw * 0.5f;
    float b2y1 = ty - th * 0.5f, b2y2 = ty + th * 0.5f;
    float iw = fmaxf(fminf(b1x2, b2x2) - fmaxf(b1x1, b2x1), 0.0f);
    float ih = fmaxf(fminf(b1y2, b2y2) - fmaxf(b1y1, b2y1), 0.0f);
    float inter = iw * ih;
    float uni = pw * ph + tw * th - inter + EPS;
    float iou = inter / uni;
    float cw = fmaxf(b1x2, b2x2) - fminf(b1x1, b2x1);
    float chh = fmaxf(b1y2, b2y2) - fminf(b1y1, b2y1);
    float c2 = cw * cw + chh * chh + EPS;
    float dx = b2x1 + b2x2 - b1x1 - b1x2;
    float dy = b2y1 + b2y2 - b1y1 - b1y2;
    float rho2 = (dx * dx + dy * dy) * 0.25f;
    float dat = atanf(tw / (th + EPS)) - atanf(pw / (ph + EPS));
    float v = 0.40528473456935108577f * dat * dat;  // 4/pi^2
    float alpha = v / (v - iou + (1.0f + EPS));
    return iou - (rho2 / c2 + v * alpha);
}

// ---------------- kernel 1: FUSED conv (NCHUNK=8) + prep --------------------
// blocks [0, 1056): full-grid objectness conv partials, 32 ch/chunk
// blocks [1056, 1127): candidate mask + compaction (tiny role)
__global__ void __launch_bounds__(128) conv_kernel(
    const float* __restrict__ f0, const float* __restrict__ f1, const float* __restrict__ f2,
    const float* __restrict__ w0, const float* __restrict__ w1, const float* __restrict__ w2,
    const float* __restrict__ tg)
{
    int tid = threadIdx.x;
    if (blockIdx.x >= CONV_BLOCKS) {
        // ---------------- prep role ----------------
        int idx = (blockIdx.x - CONV_BLOCKS) * 128 + tid;
        if (idx >= NLVL * 5 * 600) return;
        int lvl = idx / 3000, rem = idx % 3000;
        int k = rem / 600, j = rem % 600;
        int a = j / NT, t = j % NT;
        float nx = (float)c_nx[lvl];
        float gx = tg[t * 6 + 2] * nx, gy = tg[t * 6 + 3] * nx;
        float gw = tg[t * 6 + 4] * nx, gh = tg[t * 6 + 5] * nx;
        float aw, ah; anchor_wh(a, &aw, &ah);
        float rw = gw / aw, rh = gh / ah;
        float mr = fmaxf(fmaxf(rw, 1.0f / rw), fmaxf(rh, 1.0f / rh));
        bool manc = mr < 2.91f;
        bool sel;
        float gxi = nx - gx, gyi = nx - gy;
        switch (k) {
            case 0: sel = true; break;
            case 1: sel = (fmodf(gx, 1.0f)  < 0.5f) && (gx  > 1.0f); break;
            case 2: sel = (fmodf(gy, 1.0f)  < 0.5f) && (gy  > 1.0f); break;
            case 3: sel = (fmodf(gxi, 1.0f) < 0.5f) && (gxi > 1.0f); break;
            default: sel = (fmodf(gyi, 1.0f) < 0.5f) && (gyi > 1.0f); break;
        }
        if (sel && manc) {
            int pos = atomicAdd(&g_cnt[lvl * 3 + a], 1);
            g_list[(lvl * 3 + a) * MAXC + pos] = k * 600 + j;
        }
        return;
    }

    // ---------------- conv role ----------------
    __shared__ float wsm[3][CCH];
    int bid = blockIdx.x;
    int lvl, chunk, pb;
    if (bid < 800)       { lvl = 0; chunk = bid / 100; pb = bid % 100; }
    else if (bid < 1000) { int r = bid - 800;  lvl = 1; chunk = r / 25; pb = r % 25; }
    else                 { int r = bid - 1000; lvl = 2; chunk = r / 7;  pb = r % 7; }
    const float* feat = (lvl == 0) ? f0 : ((lvl == 1) ? f1 : f2);
    const float* wmat = (lvl == 0) ? w0 : ((lvl == 1) ? w1 : w2);
    int c0 = chunk * CCH;
    if (tid < 3 * CCH) {
        int a = tid / CCH, c = tid % CCH;
        wsm[a][c] = wmat[(a * NOO + 4) * CH + c0 + c];
    }
    __syncthreads();

    int P4 = c_P[lvl] >> 2;
    int idx = pb * 128 + tid;
    if (idx >= BSZ * P4) return;
    int b = idx / P4, pf4 = idx - b * P4;

    const float4* fp = reinterpret_cast<const float4*>(feat)
                     + (size_t)(b * CH + c0) * (size_t)P4 + pf4;
    float4 a0 = make_float4(0.f, 0.f, 0.f, 0.f);
    float4 a1 = a0, a2 = a0;
#pragma unroll
    for (int cc = 0; cc < CCH; cc += 8) {
        float4 v[8];
#pragma unroll
        for (int u = 0; u < 8; u++) v[u] = fp[(size_t)(cc + u) * P4];
#pragma unroll
        for (int u = 0; u < 8; u++) {
            float wv0 = wsm[0][cc + u], wv1 = wsm[1][cc + u], wv2 = wsm[2][cc + u];
            a0.x = fmaf(v[u].x, wv0, a0.x); a0.y = fmaf(v[u].y, wv0, a0.y);
            a0.z = fmaf(v[u].z, wv0, a0.z); a0.w = fmaf(v[u].w, wv0, a0.w);
            a1.x = fmaf(v[u].x, wv1, a1.x); a1.y = fmaf(v[u].y, wv1, a1.y);
            a1.z = fmaf(v[u].z, wv1, a1.z); a1.w = fmaf(v[u].w, wv1, a1.w);
            a2.x = fmaf(v[u].x, wv2, a2.x); a2.y = fmaf(v[u].y, wv2, a2.y);
            a2.z = fmaf(v[u].z, wv2, a2.z); a2.w = fmaf(v[u].w, wv2, a2.w);
        }
    }
    float4* gp = reinterpret_cast<float4*>(g_part) + (size_t)chunk * 50400;
    int base4 = c_toff4[lvl] + (b * 3) * P4 + pf4;
    gp[base4]          = a0;
    gp[base4 + P4]     = a1;
    gp[base4 + 2 * P4] = a2;
}

// ---------------- kernel 2: software-pipelined candidate GEMM ---------------
// (round-11 proven version, unchanged)
__global__ void __launch_bounds__(256) cand_kernel(
    const float* __restrict__ f0, const float* __restrict__ f1, const float* __restrict__ f2,
    const float* __restrict__ w0, const float* __restrict__ w1, const float* __restrict__ w2,
    const float* __restrict__ bp0, const float* __restrict__ bp1, const float* __restrict__ bp2,
    const float* __restrict__ tg)
{
    extern __shared__ float smb[];
    float* WsA = smb;
    float* XsA = smb + 2 * WS_STRIDE;
    float* Ps  = XsA;

    __shared__ int   sm_b[32], sm_pos[32], sm_cls[32], sm_rid[32], sm_cell[32];
    __shared__ float sm_tb[32][4];
    __shared__ float s_lb, s_c1, s_c2;

    int la = blockIdx.y;
    int lvl = la / 3, a = la % 3;
    int n = g_cnt[la];
    int m0 = blockIdx.x * 32;
    if (m0 >= n) return;
    int mcount = min(32, n - m0);
    const float* feat = (lvl == 0) ? f0 : ((lvl == 1) ? f1 : f2);
    const float* wmat = (lvl == 0) ? w0 : ((lvl == 1) ? w1 : w2);
    const float* bb   = (lvl == 0) ? bp0 : ((lvl == 1) ? bp1 : bp2);
    int nx = c_nx[lvl]; int P = c_P[lvl];
    int tid = threadIdx.x;
    if (tid == 0) { s_lb = 0.f; s_c1 = 0.f; s_c2 = 0.f; }
    if (tid < 32) {
        int m = tid;
        if (m < mcount) {
            int cid = g_list[la * MAXC + m0 + m];
            int k = cid / 600; int j = cid % 600; int t = j % NT;
            float img  = tg[t * 6 + 0], clsf = tg[t * 6 + 1];
            float gx = tg[t * 6 + 2] * (float)nx, gy = tg[t * 6 + 3] * (float)nx;
            float gw = tg[t * 6 + 4] * (float)nx, gh = tg[t * 6 + 5] * (float)nx;
            float offx = (k == 1) ? 0.5f : ((k == 3) ? -0.5f : 0.0f);
            float offy = (k == 2) ? 0.5f : ((k == 4) ? -0.5f : 0.0f);
            int gij_x = (int)(gx - offx);
            int gij_y = (int)(gy - offy);
            int gi = min(max(gij_x, 0), nx - 1);
            int gj = min(max(gij_y, 0), nx - 1);
            int b = (int)img;
            sm_b[m] = b; sm_pos[m] = gj * nx + gi;
            sm_cell[m] = ((b * NAA + a) * nx + gj) * nx + gi;
            sm_cls[m] = (int)clsf;
            sm_rid[m] = cid;
            sm_tb[m][0] = gx - (float)gij_x;
            sm_tb[m][1] = gy - (float)gij_y;
            sm_tb[m][2] = gw; sm_tb[m][3] = gh;
        } else { sm_b[m] = 0; sm_pos[m] = 0; }
    }
    __syncthreads();

    int wrp = tid >> 5, lane = tid & 31;
    int gm = tid & 31, gcb = tid >> 5;
    const float* fp = feat + (size_t)sm_b[gm] * CH * (size_t)P + sm_pos[gm];
    const float4* wsrc = reinterpret_cast<const float4*>(wmat) + (size_t)a * NOO * 64;

    {
        float4* wd = reinterpret_cast<float4*>(WsA);
        for (int i = tid; i < NOO * 16; i += 256)
            wd[i] = wsrc[(i >> 4) * 64 + (i & 15)];
#pragma unroll
        for (int r = 0; r < 8; r++)
            XsA[(gcb + 8 * r) * 32 + gm] = fp[(size_t)(gcb + 8 * r) * P];
    }
    __syncthreads();

    float acc[11];
#pragma unroll
    for (int r = 0; r < 11; r++) acc[r] = 0.0f;

    for (int kc = 0; kc < 4; kc++) {
        float* Wcur = WsA + (kc & 1) * WS_STRIDE;
        float* Xcur = XsA + (kc & 1) * XS_STRIDE;

        float xreg[8];
        float4 wreg[6];
        int widx[6];
        if (kc < 3) {
            int kn = kc + 1;
#pragma unroll
            for (int r = 0; r < 8; r++)
                xreg[r] = fp[(size_t)(kn * 64 + gcb + 8 * r) * P];
#pragma unroll
            for (int j = 0; j < 6; j++) {
                int i = tid + j * 256;
                widx[j] = i;
                if (i < NOO * 16)
                    wreg[j] = wsrc[(i >> 4) * 64 + kn * 16 + (i & 15)];
            }
        }

#pragma unroll
        for (int c4 = 0; c4 < 16; c4++) {
            float x0 = Xcur[(c4 * 4 + 0) * 32 + lane];
            float x1 = Xcur[(c4 * 4 + 1) * 32 + lane];
            float x2 = Xcur[(c4 * 4 + 2) * 32 + lane];
            float x3 = Xcur[(c4 * 4 + 3) * 32 + lane];
#pragma unroll
            for (int r = 0; r < 11; r++) {
                int o = wrp + 8 * r;
                if (o < NOO) {
                    float4 wv = *reinterpret_cast<const float4*>(&Wcur[o * 64 + c4 * 4]);
                    acc[r] = fmaf(x0, wv.x, fmaf(x1, wv.y, fmaf(x2, wv.z, fmaf(x3, wv.w, acc[r]))));
                }
            }
        }

        if (kc < 3) {
            float* Wnxt = WsA + ((kc + 1) & 1) * WS_STRIDE;
            float* Xnxt = XsA + ((kc + 1) & 1) * XS_STRIDE;
#pragma unroll
            for (int r = 0; r < 8; r++)
                Xnxt[(gcb + 8 * r) * 32 + gm] = xreg[r];
            float4* wd = reinterpret_cast<float4*>(Wnxt);
#pragma unroll
            for (int j = 0; j < 6; j++)
                if (widx[j] < NOO * 16) wd[widx[j]] = wreg[j];
        }
        __syncthreads();
    }

#pragma unroll
    for (int r = 0; r < 11; r++) {
        int o = wrp + 8 * r;
        if (o < NOO) Ps[lane * 88 + o] = acc[r] + bb[a * NOO + o];
    }
    __syncthreads();

    int m = tid >> 3, s = tid & 7;
    unsigned gmask = 0xFFu << (8 * ((tid & 31) >> 3));
    if (m < mcount) {
        float spsum = 0.f, tspm = 0.f, tspp = 0.f;
        int cls = sm_cls[m];
        for (int c = s; c < NCC; c += 8) {
            float x = Ps[m * 88 + 5 + c];
            float sp = d_spp(x);
            spsum += sp;
            if (c == cls) { tspp = sp; tspm = d_spp(-x); }
        }
        for (int off = 4; off; off >>= 1) {
            spsum += __shfl_down_sync(gmask, spsum, off, 8);
            tspm  += __shfl_down_sync(gmask, tspm,  off, 8);
            tspp  += __shfl_down_sync(gmask, tspp,  off, 8);
        }
        if (s == 0) {
            float aw, ah; anchor_wh(a, &aw, &ah);
            float px = d_sig(Ps[m * 88 + 0]) * 2.0f - 0.5f;
            float py = d_sig(Ps[m * 88 + 1]) * 2.0f - 0.5f;
            float sw = d_sig(Ps[m * 88 + 2]) * 2.0f;
            float sh = d_sig(Ps[m * 88 + 3]) * 2.0f;
            float pw = sw * sw * aw, ph = sh * sh * ah;
            float ci = d_ciou(px, py, pw, ph, sm_tb[m][0], sm_tb[m][1], sm_tb[m][2], sm_tb[m][3]);
            unsigned long long pk = ((unsigned long long)(unsigned)sm_rid[m] << 32)
                                  | (unsigned long long)__float_as_uint(fmaxf(ci, 0.0f));
            atomicMax(&g_tobj[c_toff[lvl] + sm_cell[m]], pk);
            atomicAdd(&s_lb, 1.0f - ci);
            atomicAdd(&s_c1, tspm);
            atomicAdd(&s_c2, spsum - tspp);
        }
    }
    __syncthreads();
    if (tid == 0) {
        atomicAdd(&g_acc[lvl * 8 + 0], s_lb);
        atomicAdd(&g_acc[lvl * 8 + 1], s_c1);
        atomicAdd(&g_acc[lvl * 8 + 2], s_c2);
    }
}

// ---------------- kernel 3: obj BCE + fused finalize + scratch cleanup -------
__global__ void __launch_bounds__(128) bce_kernel(
    const float* __restrict__ bp0, const float* __restrict__ bp1, const float* __restrict__ bp2,
    float* __restrict__ out)
{
    __shared__ float rbuf[3][4];
    int blk = blockIdx.x;
    int tid = threadIdx.x;
    int lvl = (blk < 300) ? 0 : ((blk < 375) ? 1 : 2);
    int gidx = blk * 128 + tid;
    float s1 = 0.f, s2 = 0.f, fg = 0.f;
    if (gidx < 50400) {
        int P4 = c_P[lvl] >> 2;
        int rel = gidx - c_toff4[lvl];
        int a = (rel / P4) % 3;
        const float* bb = (lvl == 0) ? bp0 : ((lvl == 1) ? bp1 : bp2);
        float bias = bb[a * NOO + 4];
        const float4* gp = reinterpret_cast<const float4*>(g_part);
        float xs[4] = {bias, bias, bias, bias};
#pragma unroll
        for (int k = 0; k < NCHUNK; k++) {
            float4 p = gp[(size_t)k * 50400 + gidx];
            xs[0] += p.x; xs[1] += p.y; xs[2] += p.z; xs[3] += p.w;
        }
        ulonglong2* tp = reinterpret_cast<ulonglong2*>(&g_tobj[(size_t)gidx * 4]);
        ulonglong2 t01 = tp[0];
        ulonglong2 t23 = tp[1];
        tp[0] = make_ulonglong2(0ull, 0ull);   // self-clean
        tp[1] = make_ulonglong2(0ull, 0ull);
        unsigned long long tv[4] = {t01.x, t01.y, t23.x, t23.y};
#pragma unroll
        for (int j = 0; j < 4; j++) {
            float x = xs[j];
            float t = __uint_as_float((unsigned)tv[j]);
            float l = log1pf(expf(-fabsf(x)));
            float spp = fmaxf(x, 0.f) + l;
            float spm = fmaxf(-x, 0.f) + l;
            s1 += t * spm;
            s2 += (1.0f - t) * spp;
            fg += (t > 0.f) ? 1.0f : 0.0f;
        }
    }
    for (int off = 16; off; off >>= 1) {
        s1 += __shfl_down_sync(0xffffffffu, s1, off);
        s2 += __shfl_down_sync(0xffffffffu, s2, off);
        fg += __shfl_down_sync(0xffffffffu, fg, off);
    }
    if ((tid & 31) == 0) { rbuf[0][tid >> 5] = s1; rbuf[1][tid >> 5] = s2; rbuf[2][tid >> 5] = fg; }
    __syncthreads();
    bool last = false;
    if (tid == 0) {
        float t1 = 0.f, t2 = 0.f, t3 = 0.f;
        for (int i = 0; i < 4; i++) { t1 += rbuf[0][i]; t2 += rbuf[1][i]; t3 += rbuf[2][i]; }
        atomicAdd(&g_acc[lvl * 8 + 3], t1);
        atomicAdd(&g_acc[lvl * 8 + 4], t2);
        atomicAdd(&g_acc[lvl * 8 + 5], t3);
        __threadfence();
        int done = atomicAdd(&g_bcnt, 1);
        last = (done == 393);
    }
    if (last) {
        float lbox = 0.f, lobj = 0.f, lcls = 0.f;
        const float bal[3] = {4.0f, 1.0f, 0.25f};
        for (int l = 0; l < 3; l++) {
            float nv = (float)(g_cnt[l * 3] + g_cnt[l * 3 + 1] + g_cnt[l * 3 + 2]);
            float lb = atomicAdd(&g_acc[l * 8 + 0], 0.0f);
            float c1 = atomicAdd(&g_acc[l * 8 + 1], 0.0f);
            float c2 = atomicAdd(&g_acc[l * 8 + 2], 0.0f);
            float S1 = atomicAdd(&g_acc[l * 8 + 3], 0.0f);
            float S2 = atomicAdd(&g_acc[l * 8 + 4], 0.0f);
            float fgc = atomicAdd(&g_acc[l * 8 + 5], 0.0f);
            lbox += lb / fmaxf(nv, 1.0f);
            float pwc = nv * (float)(NCC - 1) * 0.5f / fmaxf(nv, 2.0f);
            lcls += (pwc * c1 + c2) / fmaxf(nv * (float)NCC, 1.0f);
            float cnt = (float)(BSZ * NAA * c_P[l]);
            float bg = cnt - fgc;
            float pwo = bg * 0.5f / fmaxf(fgc, 2.0f);
            lobj += (pwo * S1 + S2) / cnt * bal[l];
        }
        out[0] = lbox * 0.05f;
        out[1] = lobj * 1.0f;
        out[2] = lcls * 0.5f;
        for (int i = 0; i < 32; i++) g_acc[i] = 0.0f;
        for (int i = 0; i < 16; i++) g_cnt[i] = 0;
        g_bcnt = 0;
    }
}

// ---------------- launch -----------------------------------------------------
extern "C" void kernel_launch(void* const* d_in, const int* in_sizes, int n_in,
                              void* d_out, int out_size) {
    const float *f[3], *w[3], *b[3], *tg;
    if (n_in >= 10 && in_sizes[1] == 65280) {
        f[0] = (const float*)d_in[0]; w[0] = (const float*)d_in[1]; b[0] = (const float*)d_in[2];
        f[1] = (const float*)d_in[3]; w[1] = (const float*)d_in[4]; b[1] = (const float*)d_in[5];
        f[2] = (const float*)d_in[6]; w[2] = (const float*)d_in[7]; b[2] = (const float*)d_in[8];
        tg = (const float*)d_in[9];
    } else {
        f[0] = (const float*)d_in[0]; f[1] = (const float*)d_in[1]; f[2] = (const float*)d_in[2];
        w[0] = (const float*)d_in[3]; w[1] = (const float*)d_in[4]; w[2] = (const float*)d_in[5];
        b[0] = (const float*)d_in[6]; b[1] = (const float*)d_in[7]; b[2] = (const float*)d_in[8];
        tg = (const float*)d_in[9];
    }

    static bool s_init = false;
    if (!s_init) {
        cudaFuncSetAttribute(cand_kernel,
                             cudaFuncAttributeMaxDynamicSharedMemorySize, CAND_SMEM);
        s_init = true;
    }

    conv_kernel<<<CONV_BLOCKS + PREP_BLOCKS, 128>>>(f[0], f[1], f[2],
                                                    w[0], w[1], w[2], tg);
    cand_kernel<<<dim3(32, 9), 256, CAND_SMEM>>>(f[0], f[1], f[2], w[0], w[1], w[2],
                                                 b[0], b[1], b[2], tg);
    bce_kernel<<<394, 128>>>(b[0], b[1], b[2], (float*)d_out);
}